// round 16
// baseline (speedup 1.0000x reference)
#include <cuda_runtime.h>
#include <cuda_fp16.h>
#include <math.h>
#include <stdint.h>

typedef unsigned int u32;
typedef unsigned long long u64;

#define BDIM 16
#define CDIM 256
#define NDIM 2048
#define OTOT 320
#define EPSV 1e-5f
#define LOG2E 1.4426950408889634f

__device__ __align__(16) float g_proj[(size_t)BDIM * 64 * NDIM];   // Q/K channels only
__device__ __align__(16) u32 g_w16h[OTOT * 128];
__device__ __align__(16) __half g_q16[(size_t)BDIM * NDIM * 32];   // [b][n][32]
__device__ __align__(16) __half g_k16[(size_t)BDIM * NDIM * 32];   // [b][m][32]
__device__ __align__(16) __half g_v16[(size_t)BDIM * CDIM * NDIM]; // [b][c][m]
__device__ float g_ps1[OTOT * 128];
__device__ float g_ps2[OTOT * 128];
__device__ float g_scale[OTOT];
__device__ float g_shift[OTOT];

// ---------------- helpers ----------------
__device__ __forceinline__ u64 dup2(float v) {
    u64 r; asm("mov.b64 %0, {%1, %1};" : "=l"(r) : "f"(v)); return r;
}
__device__ __forceinline__ u64 mul2(u64 a, u64 b) {
    u64 r; asm("mul.rn.f32x2 %0, %1, %2;" : "=l"(r) : "l"(a), "l"(b)); return r;
}
__device__ __forceinline__ float ex2(float x) {
    float r; asm("ex2.approx.f32 %0, %1;" : "=f"(r) : "f"(x)); return r;
}
__device__ __forceinline__ u32 smem_u32(const void* p) {
    u32 a; asm("{ .reg .u64 t; cvta.to.shared.u64 t, %1; cvt.u32.u64 %0, t; }" : "=r"(a) : "l"(p));
    return a;
}
__device__ __forceinline__ void mma16(float d[4], const u32 a[4], u32 b0, u32 b1) {
    asm volatile("mma.sync.aligned.m16n8k16.row.col.f32.f16.f16.f32 "
                 "{%0,%1,%2,%3}, {%4,%5,%6,%7}, {%8,%9}, {%0,%1,%2,%3};"
                 : "+f"(d[0]), "+f"(d[1]), "+f"(d[2]), "+f"(d[3])
                 : "r"(a[0]), "r"(a[1]), "r"(a[2]), "r"(a[3]), "r"(b0), "r"(b1));
}
#define CP16(dst, src) asm volatile("cp.async.cg.shared.global [%0], [%1], 16;" :: "r"(dst), "l"(src))
#define CP_COMMIT()    asm volatile("cp.async.commit_group;" ::: "memory")
#define CP_WAIT0()     asm volatile("cp.async.wait_group 0;" ::: "memory")

// ================= Kernel 0: W -> fp16 (hi only) =================
__global__ void __launch_bounds__(128) w16_kernel(
    const float* __restrict__ qw, const float* __restrict__ kw, const float* __restrict__ vw)
{
    const int o = blockIdx.x, t = threadIdx.x;
    const float* row = o < 32 ? qw + (size_t)o * CDIM
                     : o < 64 ? kw + (size_t)(o - 32) * CDIM
                              : vw + (size_t)(o - 64) * CDIM;
    __half2 hh = __floats2half2_rn(row[2 * t], row[2 * t + 1]);
    g_w16h[o * 128 + t] = *(u32*)&hh;
}

// ================= Kernel 1: QKV projection (fp16 mma, 1-pass) + fused stats =====
__global__ void __launch_bounds__(256) proj16_kernel(const float* __restrict__ x)
{
    __shared__ u32 xs_h[2][2048];
    __shared__ float2 sm_sp[128];
    const int tid = threadIdx.x, wid = tid >> 5, lane = tid & 31;
    const int tg = lane >> 2, tq = lane & 3;
    const int wo = wid & 3, wn = wid >> 2;
    const int ob = blockIdx.x * 64 + wo * 16;
    const int gn0 = blockIdx.y * 256, b = blockIdx.z;
    const float* xb = x + (size_t)b * CDIM * NDIM + gn0;
    const int pn = tid;

    float acc[16][4];
#pragma unroll
    for (int nf = 0; nf < 16; nf++)
#pragma unroll
        for (int j = 0; j < 4; j++) acc[nf][j] = 0.0f;

    float stg[8][2];
    auto ldg = [&](int t1) {
#pragma unroll
        for (int cp = 0; cp < 8; cp++) {
            int c = t1 * 16 + 2 * cp;
            stg[cp][0] = xb[(size_t)c * NDIM + pn];
            stg[cp][1] = xb[(size_t)(c + 1) * NDIM + pn];
        }
    };
    auto sts = [&](int buf) {
#pragma unroll
        for (int cp = 0; cp < 8; cp++) {
            __half2 hh = __floats2half2_rn(stg[cp][0], stg[cp][1]);
            xs_h[buf][cp * 256 + (pn ^ (cp << 3))] = *(u32*)&hh;
        }
    };

    ldg(0); sts(0);
    __syncthreads();

    for (int t = 0; t < 16; t++) {
        if (t < 15) ldg(t + 1);
        const int buf = t & 1;
        u32 ah[4];
        {
            size_t r = (size_t)(ob + tg) * 128 + 8 * t + tq;
            ah[0] = g_w16h[r];            ah[1] = g_w16h[r + 8 * 128];
            ah[2] = g_w16h[r + 4];        ah[3] = g_w16h[r + 8 * 128 + 4];
        }
#pragma unroll
        for (int nf = 0; nf < 16; nf++) {
            const int nl = wn * 128 + 8 * nf + tg;
            u32 bh0 = xs_h[buf][tq * 256 + (nl ^ (tq << 3))];
            u32 bh1 = xs_h[buf][(tq + 4) * 256 + (nl ^ ((tq + 4) << 3))];
            mma16(acc[nf], ah, bh0, bh1);
        }
        if (t < 15) sts((t + 1) & 1);
        __syncthreads();
    }

    if (blockIdx.x == 0) {
#pragma unroll
        for (int nf = 0; nf < 16; nf++) {
            const int n = gn0 + wn * 128 + 8 * nf + 2 * tq;
            size_t base = ((size_t)b * 64 + ob + tg) * NDIM + n;
            *reinterpret_cast<float2*>(&g_proj[base]) = make_float2(acc[nf][0], acc[nf][1]);
            *reinterpret_cast<float2*>(&g_proj[base + (size_t)8 * NDIM]) = make_float2(acc[nf][2], acc[nf][3]);
        }
    } else {
        const int cb = ob - 64;
#pragma unroll
        for (int nf = 0; nf < 16; nf++) {
            const int n = gn0 + wn * 128 + 8 * nf + 2 * tq;
            size_t base = ((size_t)b * CDIM + cb + tg) * NDIM + n;
            __half2 h0 = __floats2half2_rn(acc[nf][0], acc[nf][1]);
            __half2 h1 = __floats2half2_rn(acc[nf][2], acc[nf][3]);
            *reinterpret_cast<u32*>(&g_v16[base]) = *(u32*)&h0;
            *reinterpret_cast<u32*>(&g_v16[base + (size_t)8 * NDIM]) = *(u32*)&h1;
        }
    }

    float s0 = 0.f, q0 = 0.f, s1 = 0.f, q1 = 0.f;
#pragma unroll
    for (int nf = 0; nf < 16; nf++) {
        s0 += acc[nf][0] + acc[nf][1];
        q0 += acc[nf][0] * acc[nf][0] + acc[nf][1] * acc[nf][1];
        s1 += acc[nf][2] + acc[nf][3];
        q1 += acc[nf][2] * acc[nf][2] + acc[nf][3] * acc[nf][3];
    }
#pragma unroll
    for (int off = 1; off < 4; off <<= 1) {
        s0 += __shfl_xor_sync(0xffffffffu, s0, off);
        q0 += __shfl_xor_sync(0xffffffffu, q0, off);
        s1 += __shfl_xor_sync(0xffffffffu, s1, off);
        q1 += __shfl_xor_sync(0xffffffffu, q1, off);
    }
    if (tq == 0) {
        sm_sp[wid * 16 + tg]     = make_float2(s0, q0);
        sm_sp[wid * 16 + 8 + tg] = make_float2(s1, q1);
    }
    __syncthreads();
    if (tid < 64) {
        int wo2 = tid >> 4, c = tid & 15;
        float2 a = sm_sp[wo2 * 16 + c];
        float2 e = sm_sp[(wo2 + 4) * 16 + c];
        int ch = blockIdx.x * 64 + wo2 * 16 + c;
        g_ps1[ch * 128 + b * 8 + blockIdx.y] = a.x + e.x;
        g_ps2[ch * 128 + b * 8 + blockIdx.y] = a.y + e.y;
    }
}

// ================= Kernel 2: finalize stats =================
__global__ void __launch_bounds__(128) stats_fin(
    const float* __restrict__ qg, const float* __restrict__ qbe,
    const float* __restrict__ kg, const float* __restrict__ kbe,
    const float* __restrict__ vg, const float* __restrict__ vbe)
{
    const int ch = blockIdx.x, tid = threadIdx.x;
    __shared__ float r1[128], r2[128];
    r1[tid] = g_ps1[ch * 128 + tid];
    r2[tid] = g_ps2[ch * 128 + tid];
    __syncthreads();
    for (int off = 64; off; off >>= 1) {
        if (tid < off) { r1[tid] += r1[tid + off]; r2[tid] += r2[tid + off]; }
        __syncthreads();
    }
    if (tid == 0) {
        const float invM = 1.0f / (float)(BDIM * NDIM);
        float mean = r1[0] * invM;
        float var = r2[0] * invM - mean * mean;
        float gamma, beta;
        if (ch < 32)      { gamma = qg[ch];      beta = qbe[ch]; }
        else if (ch < 64) { gamma = kg[ch - 32]; beta = kbe[ch - 32]; }
        else              { gamma = vg[ch - 64]; beta = vbe[ch - 64]; }
        float sc = gamma * rsqrtf(var + EPSV);
        g_scale[ch] = sc;
        g_shift[ch] = beta - mean * sc;
    }
}

// ================= Kernel 3: Q/K normalize + transpose -> fp16 (Q pre-scaled log2e) =======
__global__ void __launch_bounds__(256) qkt_kernel()
{
    __shared__ float s[64][65];
    __shared__ float scl[64], shf[64];
    const int tid = threadIdx.x;
    const int n0 = blockIdx.x * 64, b = blockIdx.y;
    if (tid < 64) {
        float f = (tid < 32) ? LOG2E : 1.0f;
        scl[tid] = g_scale[tid] * f;
        shf[tid] = g_shift[tid] * f;
    }
    __syncthreads();
    for (int idx = tid; idx < 4096; idx += 256) {
        int ch = idx >> 6, nn = idx & 63;
        s[ch][nn] = g_proj[((size_t)b * 64 + ch) * NDIM + n0 + nn] * scl[ch] + shf[ch];
    }
    __syncthreads();
    const int n = tid >> 2, d0 = (tid & 3) * 8;
    const size_t row = ((size_t)b * NDIM + n0 + n) * 32;
#pragma unroll
    for (int qk = 0; qk < 2; qk++) {
        __half* dst = (qk ? g_k16 : g_q16) + row;
        u32 wh[4];
#pragma unroll
        for (int j = 0; j < 4; j++) {
            __half2 hh = __floats2half2_rn(s[qk * 32 + d0 + 2 * j][n],
                                           s[qk * 32 + d0 + 2 * j + 1][n]);
            wh[j] = *(u32*)&hh;
        }
        *reinterpret_cast<uint4*>(dst + d0) = make_uint4(wh[0], wh[1], wh[2], wh[3]);
    }
}

// ================= Kernel 4: V in-place normalize + leaky =================
__global__ void __launch_bounds__(256) v16_kernel()
{
    const int b = blockIdx.y, tid = threadIdx.x;
    const int i4 = blockIdx.x * 256 + tid;
    const int off = i4 * 4;
    const int c = off >> 11, n = off & 2047;
    const float sc = g_scale[64 + c], sh = g_shift[64 + c];
    __half* p = &g_v16[((size_t)b * CDIM + c) * NDIM + n];
    uint2 w = *reinterpret_cast<const uint2*>(p);
    __half2 h0 = *(__half2*)&w.x, h1 = *(__half2*)&w.y;
    float2 f0 = __half22float2(h0), f1 = __half22float2(h1);
    float a0 = f0.x * sc + sh, a1 = f0.y * sc + sh;
    float a2 = f1.x * sc + sh, a3 = f1.y * sc + sh;
    a0 = a0 > 0.f ? a0 : 0.2f * a0; a1 = a1 > 0.f ? a1 : 0.2f * a1;
    a2 = a2 > 0.f ? a2 : 0.2f * a2; a3 = a3 > 0.f ? a3 : 0.2f * a3;
    __half2 p0 = __floats2half2_rn(a0, a1), p1 = __floats2half2_rn(a2, a3);
    *reinterpret_cast<uint2*>(p) = make_uint2(*(u32*)&p0, *(u32*)&p1);
}

// ================= Kernel 5: pipelined fp16 flash attention =====
// V x3, P x2; PV(t-1) issued after S(t) so softmax overlaps tensor work.
#define OFF_K0 0
#define OFF_K1 5120
#define OFF_V  10240
#define VSZ    36864
#define OFF_P  120832
#define PSZ    9216
#define OFF_A  139264
#define OFF_RM 139776
#define OFF_LS 140288
#define SMEM_TOTAL 140800

__global__ void __launch_bounds__(256, 1) attn_kernel(
    const float* __restrict__ x, float* __restrict__ out)
{
    extern __shared__ __align__(16) char smc[];
    const u32 sb = smem_u32(smc);
    float* Abuf = (float*)(smc + OFF_A);    // [2][64]
    float* Rm   = (float*)(smc + OFF_RM);   // [2][64]
    float* Lsm  = (float*)(smc + OFF_LS);   // [2][64]

    const int tid = threadIdx.x, wid = tid >> 5, lane = tid & 31;
    const int wm = wid & 3, wc = wid >> 2;
    const int tg = lane >> 2, tq = lane & 3;
    const int n0 = blockIdx.x * 64, b = blockIdx.y;
    const int r0 = 16 * wm + tg;

    u32 qh[2][4];
    {
        const __half* Qg = g_q16 + ((size_t)b * NDIM + n0) * 32;
#pragma unroll
        for (int kk = 0; kk < 2; kk++) {
            int d = kk * 16 + 2 * tq;
            qh[kk][0] = *(const u32*)(Qg + (size_t)r0 * 32 + d);
            qh[kk][1] = *(const u32*)(Qg + (size_t)(r0 + 8) * 32 + d);
            qh[kk][2] = *(const u32*)(Qg + (size_t)r0 * 32 + d + 8);
            qh[kk][3] = *(const u32*)(Qg + (size_t)(r0 + 8) * 32 + d + 8);
        }
    }

    float acc[4][4][4];
#pragma unroll
    for (int mj = 0; mj < 4; mj++)
#pragma unroll
        for (int nf = 0; nf < 4; nf++)
#pragma unroll
            for (int j = 0; j < 4; j++) acc[mj][nf][j] = 0.0f;

    float M0 = -INFINITY, M1 = -INFINITY, L0 = 0.0f, L1 = 0.0f;

    auto issue_tile = [&](int m0, int t) {
        u32 kb = sb + ((t & 1) ? OFF_K1 : OFF_K0);
        u32 vb = sb + OFF_V + (u32)(t % 3) * VSZ;
        const __half* Kg = g_k16 + ((size_t)b * NDIM + m0) * 32;
        const __half* Vg = g_v16 + (size_t)b * CDIM * NDIM + m0;
#pragma unroll
        for (int i = 0; i < 9; i++) {
            int id = tid + i * 256;
            if (id < 256) {
                int m = id >> 2, ch = id & 3;
                CP16(kb + m * 80 + ch * 16, Kg + (size_t)m * 32 + ch * 8);
            } else {
                int j = id - 256, c = j >> 3, ch = j & 7;
                CP16(vb + c * 144 + ch * 16, Vg + (size_t)c * NDIM + ch * 8);
            }
        }
        CP_COMMIT();
    };

    auto do_pv = [&](int t) {   // rescale acc by alpha(t) then acc += P(t) V(t)
        const float* Ab = Abuf + (t & 1) * 64;
        const char* P = smc + OFF_P + (t & 1) * PSZ;
        const char* V = smc + OFF_V + (t % 3) * VSZ;
#pragma unroll
        for (int mj = 0; mj < 4; mj++) {
            const float a0 = Ab[16 * mj + tg], a1 = Ab[16 * mj + tg + 8];
            if (__all_sync(0xffffffffu, (a0 == 1.0f) && (a1 == 1.0f))) continue;
            const u64 A0 = dup2(a0), A1 = dup2(a1);
#pragma unroll
            for (int nf = 0; nf < 4; nf++) {
                u64* pa = reinterpret_cast<u64*>(acc[mj][nf]);
                pa[0] = mul2(pa[0], A0);
                pa[1] = mul2(pa[1], A1);
            }
        }
#pragma unroll
        for (int kk = 0; kk < 4; kk++) {
            const int m = kk * 16 + 2 * tq;
            u32 af[4][4];
#pragma unroll
            for (int mj = 0; mj < 4; mj++) {
                const int rr = 16 * mj + tg;
                af[mj][0] = *(const u32*)(P + rr * 144 + m * 2);
                af[mj][1] = *(const u32*)(P + (rr + 8) * 144 + m * 2);
                af[mj][2] = *(const u32*)(P + rr * 144 + (m + 8) * 2);
                af[mj][3] = *(const u32*)(P + (rr + 8) * 144 + (m + 8) * 2);
            }
#pragma unroll
            for (int nf = 0; nf < 4; nf++) {
                const char* vrow = V + (32 * wid + 8 * nf + tg) * 144;
                u32 b0 = *(const u32*)(vrow + m * 2);
                u32 b1 = *(const u32*)(vrow + (m + 8) * 2);
#pragma unroll
                for (int mj = 0; mj < 4; mj++)
                    mma16(acc[mj][nf], af[mj], b0, b1);
            }
        }
    };

    issue_tile(0, 0);

    for (int t = 0; t < 32; t++) {
        CP_WAIT0();
        __syncthreads();   // bar1: K/V(t) ready; all warps done iter t-1 (P(t-1), Abuf(t-1) visible)
        if (t < 31) issue_tile((t + 1) * 64, t + 1);

        // ---- S(t) mma (issued first: results needed soonest) ----
        const char* K = smc + ((t & 1) ? OFF_K1 : OFF_K0);
        float sf[4][4];
#pragma unroll
        for (int nf = 0; nf < 4; nf++) {
#pragma unroll
            for (int j = 0; j < 4; j++) sf[nf][j] = 0.0f;
            const char* krow = K + (32 * wc + 8 * nf + tg) * 80;
#pragma unroll
            for (int kk = 0; kk < 2; kk++) {
                int d = kk * 16 + 2 * tq;
                u32 bh0 = *(const u32*)(krow + d * 2);
                u32 bh1 = *(const u32*)(krow + (d + 8) * 2);
                mma16(sf[nf], qh[kk], bh0, bh1);
            }
        }

        // ---- PV(t-1): keeps tensor pipe busy while softmax(t) runs ----
        if (t > 0) do_pv(t - 1);

        // ---- row max (waits only on S(t)) ----
        float rm0 = fmaxf(fmaxf(sf[0][0], sf[0][1]), fmaxf(sf[1][0], sf[1][1]));
        rm0 = fmaxf(rm0, fmaxf(fmaxf(sf[2][0], sf[2][1]), fmaxf(sf[3][0], sf[3][1])));
        float rm1 = fmaxf(fmaxf(sf[0][2], sf[0][3]), fmaxf(sf[1][2], sf[1][3]));
        rm1 = fmaxf(rm1, fmaxf(fmaxf(sf[2][2], sf[2][3]), fmaxf(sf[3][2], sf[3][3])));
        rm0 = fmaxf(rm0, __shfl_xor_sync(0xffffffffu, rm0, 1));
        rm0 = fmaxf(rm0, __shfl_xor_sync(0xffffffffu, rm0, 2));
        rm1 = fmaxf(rm1, __shfl_xor_sync(0xffffffffu, rm1, 1));
        rm1 = fmaxf(rm1, __shfl_xor_sync(0xffffffffu, rm1, 2));
        if (tq == 0) { Rm[wc * 64 + r0] = rm0; Rm[wc * 64 + r0 + 8] = rm1; }
        asm volatile("bar.sync %0, 64;" :: "r"(wm + 1) : "memory");

        // ---- softmax (register M/L; base-2) ----
        const float nm0 = fmaxf(M0, fmaxf(Rm[r0], Rm[64 + r0]));
        const float nm1 = fmaxf(M1, fmaxf(Rm[r0 + 8], Rm[64 + r0 + 8]));
        const float al0 = ex2(M0 - nm0), al1 = ex2(M1 - nm1);
        M0 = nm0; M1 = nm1;
        char* Pw = smc + OFF_P + (t & 1) * PSZ;
        float lp0 = 0.0f, lp1 = 0.0f;
#pragma unroll
        for (int nf = 0; nf < 4; nf++) {
            __half2 h01 = __floats2half2_rn(ex2(sf[nf][0] - nm0), ex2(sf[nf][1] - nm0));
            __half2 h23 = __floats2half2_rn(ex2(sf[nf][2] - nm1), ex2(sf[nf][3] - nm1));
            float2 f01 = __half22float2(h01), f23 = __half22float2(h23);
            lp0 += f01.x + f01.y; lp1 += f23.x + f23.y;
            const int col = 32 * wc + 8 * nf + 2 * tq;
            *(u32*)(Pw + r0 * 144 + col * 2) = *(u32*)&h01;
            *(u32*)(Pw + (r0 + 8) * 144 + col * 2) = *(u32*)&h23;
        }
        lp0 += __shfl_xor_sync(0xffffffffu, lp0, 1);
        lp0 += __shfl_xor_sync(0xffffffffu, lp0, 2);
        lp1 += __shfl_xor_sync(0xffffffffu, lp1, 1);
        lp1 += __shfl_xor_sync(0xffffffffu, lp1, 2);
        L0 = L0 * al0 + lp0;
        L1 = L1 * al1 + lp1;
        if (wc == 0 && tq == 0) {
            Abuf[(t & 1) * 64 + r0] = al0;
            Abuf[(t & 1) * 64 + r0 + 8] = al1;
        }
        // next bar1 publishes P(t) + Abuf(t) to all warps
    }

    // ---- tail: PV(31) ----
    __syncthreads();
    do_pv(31);

    // ---- combine L halves ----
    if (tq == 0) { Lsm[wc * 64 + r0] = L0; Lsm[wc * 64 + r0 + 8] = L1; }
    __syncthreads();

    // ---- epilogue: O/L + residual ----
#pragma unroll
    for (int mj = 0; mj < 4; mj++) {
        const int rr = 16 * mj + tg;
        const float il0 = 1.0f / (Lsm[rr] + Lsm[64 + rr]);
        const float il1 = 1.0f / (Lsm[rr + 8] + Lsm[64 + rr + 8]);
#pragma unroll
        for (int nf = 0; nf < 4; nf++) {
            const int c = 32 * wid + 8 * nf + 2 * tq;
            size_t g00 = ((size_t)b * CDIM + c) * NDIM + n0 + rr;
            size_t g01 = g00 + NDIM;
            size_t g10 = g00 + 8;
            size_t g11 = g01 + 8;
            out[g00] = acc[mj][nf][0] * il0 + x[g00];
            out[g01] = acc[mj][nf][1] * il0 + x[g01];
            out[g10] = acc[mj][nf][2] * il1 + x[g10];
            out[g11] = acc[mj][nf][3] * il1 + x[g11];
        }
    }
}

extern "C" void kernel_launch(void* const* d_in, const int* in_sizes, int n_in,
                              void* d_out, int out_size) {
    const float* x    = (const float*)d_in[0];
    const float* q_w  = (const float*)d_in[1];
    const float* q_g  = (const float*)d_in[3];
    const float* q_be = (const float*)d_in[4];
    const float* k_w  = (const float*)d_in[5];
    const float* k_g  = (const float*)d_in[7];
    const float* k_be = (const float*)d_in[8];
    const float* v_w  = (const float*)d_in[9];
    const float* v_g  = (const float*)d_in[11];
    const float* v_be = (const float*)d_in[12];
    float* out = (float*)d_out;

    w16_kernel<<<OTOT, 128>>>(q_w, k_w, v_w);
    proj16_kernel<<<dim3(5, 8, 16), 256>>>(x);
    stats_fin<<<OTOT, 128>>>(q_g, q_be, k_g, k_be, v_g, v_be);
    qkt_kernel<<<dim3(32, 16), 256>>>();
    v16_kernel<<<dim3(512, 16), 256>>>();

    static int smem_set = 0;
    if (!smem_set) {
        cudaFuncSetAttribute(attn_kernel, cudaFuncAttributeMaxDynamicSharedMemorySize, SMEM_TOTAL);
        smem_set = 1;
    }
    attn_kernel<<<dim3(32, 16), 256, SMEM_TOTAL>>>(x, out);
}

// round 17
// speedup vs baseline: 1.2111x; 1.2111x over previous
#include <cuda_runtime.h>
#include <cuda_fp16.h>
#include <math.h>
#include <stdint.h>

typedef unsigned int u32;
typedef unsigned long long u64;

#define BDIM 16
#define CDIM 256
#define NDIM 2048
#define OTOT 320
#define EPSV 1e-5f
#define LOG2E 1.4426950408889634f

__device__ __align__(16) float g_proj[(size_t)BDIM * 64 * NDIM];   // Q/K channels only
__device__ __align__(16) u32 g_w16h[OTOT * 128];
__device__ __align__(16) __half g_q16[(size_t)BDIM * NDIM * 32];   // [b][n][32]
__device__ __align__(16) __half g_k16[(size_t)BDIM * NDIM * 32];   // [b][m][32]
__device__ __align__(16) __half g_v16[(size_t)BDIM * CDIM * NDIM]; // [b][c][m]
__device__ float g_ps1[OTOT * 128];
__device__ float g_ps2[OTOT * 128];
__device__ float g_scale[OTOT];
__device__ float g_shift[OTOT];

// ---------------- helpers ----------------
__device__ __forceinline__ u64 dup2(float v) {
    u64 r; asm("mov.b64 %0, {%1, %1};" : "=l"(r) : "f"(v)); return r;
}
__device__ __forceinline__ u64 mul2(u64 a, u64 b) {
    u64 r; asm("mul.rn.f32x2 %0, %1, %2;" : "=l"(r) : "l"(a), "l"(b)); return r;
}
__device__ __forceinline__ float ex2(float x) {
    float r; asm("ex2.approx.f32 %0, %1;" : "=f"(r) : "f"(x)); return r;
}
__device__ __forceinline__ u32 smem_u32(const void* p) {
    u32 a; asm("{ .reg .u64 t; cvta.to.shared.u64 t, %1; cvt.u32.u64 %0, t; }" : "=r"(a) : "l"(p));
    return a;
}
__device__ __forceinline__ void mma16(float d[4], const u32 a[4], u32 b0, u32 b1) {
    asm volatile("mma.sync.aligned.m16n8k16.row.col.f32.f16.f16.f32 "
                 "{%0,%1,%2,%3}, {%4,%5,%6,%7}, {%8,%9}, {%0,%1,%2,%3};"
                 : "+f"(d[0]), "+f"(d[1]), "+f"(d[2]), "+f"(d[3])
                 : "r"(a[0]), "r"(a[1]), "r"(a[2]), "r"(a[3]), "r"(b0), "r"(b1));
}
#define CP16(dst, src) asm volatile("cp.async.cg.shared.global [%0], [%1], 16;" :: "r"(dst), "l"(src))
#define CP_COMMIT()    asm volatile("cp.async.commit_group;" ::: "memory")
#define CP_WAIT0()     asm volatile("cp.async.wait_group 0;" ::: "memory")

// ================= Kernel 0: W -> fp16 (hi only) =================
__global__ void __launch_bounds__(128) w16_kernel(
    const float* __restrict__ qw, const float* __restrict__ kw, const float* __restrict__ vw)
{
    const int o = blockIdx.x, t = threadIdx.x;
    const float* row = o < 32 ? qw + (size_t)o * CDIM
                     : o < 64 ? kw + (size_t)(o - 32) * CDIM
                              : vw + (size_t)(o - 64) * CDIM;
    __half2 hh = __floats2half2_rn(row[2 * t], row[2 * t + 1]);
    g_w16h[o * 128 + t] = *(u32*)&hh;
}

// ================= Kernel 1: QKV projection (fp16 mma, 1-pass) + fused stats =====
__global__ void __launch_bounds__(256) proj16_kernel(const float* __restrict__ x)
{
    __shared__ u32 xs_h[2][2048];
    __shared__ float2 sm_sp[128];
    const int tid = threadIdx.x, wid = tid >> 5, lane = tid & 31;
    const int tg = lane >> 2, tq = lane & 3;
    const int wo = wid & 3, wn = wid >> 2;
    const int ob = blockIdx.x * 64 + wo * 16;
    const int gn0 = blockIdx.y * 256, b = blockIdx.z;
    const float* xb = x + (size_t)b * CDIM * NDIM + gn0;
    const int pn = tid;

    float acc[16][4];
#pragma unroll
    for (int nf = 0; nf < 16; nf++)
#pragma unroll
        for (int j = 0; j < 4; j++) acc[nf][j] = 0.0f;

    float stg[8][2];
    auto ldg = [&](int t1) {
#pragma unroll
        for (int cp = 0; cp < 8; cp++) {
            int c = t1 * 16 + 2 * cp;
            stg[cp][0] = xb[(size_t)c * NDIM + pn];
            stg[cp][1] = xb[(size_t)(c + 1) * NDIM + pn];
        }
    };
    auto sts = [&](int buf) {
#pragma unroll
        for (int cp = 0; cp < 8; cp++) {
            __half2 hh = __floats2half2_rn(stg[cp][0], stg[cp][1]);
            xs_h[buf][cp * 256 + (pn ^ (cp << 3))] = *(u32*)&hh;
        }
    };

    ldg(0); sts(0);
    __syncthreads();

    for (int t = 0; t < 16; t++) {
        if (t < 15) ldg(t + 1);
        const int buf = t & 1;
        u32 ah[4];
        {
            size_t r = (size_t)(ob + tg) * 128 + 8 * t + tq;
            ah[0] = g_w16h[r];            ah[1] = g_w16h[r + 8 * 128];
            ah[2] = g_w16h[r + 4];        ah[3] = g_w16h[r + 8 * 128 + 4];
        }
#pragma unroll
        for (int nf = 0; nf < 16; nf++) {
            const int nl = wn * 128 + 8 * nf + tg;
            u32 bh0 = xs_h[buf][tq * 256 + (nl ^ (tq << 3))];
            u32 bh1 = xs_h[buf][(tq + 4) * 256 + (nl ^ ((tq + 4) << 3))];
            mma16(acc[nf], ah, bh0, bh1);
        }
        if (t < 15) sts((t + 1) & 1);
        __syncthreads();
    }

    if (blockIdx.x == 0) {
#pragma unroll
        for (int nf = 0; nf < 16; nf++) {
            const int n = gn0 + wn * 128 + 8 * nf + 2 * tq;
            size_t base = ((size_t)b * 64 + ob + tg) * NDIM + n;
            *reinterpret_cast<float2*>(&g_proj[base]) = make_float2(acc[nf][0], acc[nf][1]);
            *reinterpret_cast<float2*>(&g_proj[base + (size_t)8 * NDIM]) = make_float2(acc[nf][2], acc[nf][3]);
        }
    } else {
        const int cb = ob - 64;
#pragma unroll
        for (int nf = 0; nf < 16; nf++) {
            const int n = gn0 + wn * 128 + 8 * nf + 2 * tq;
            size_t base = ((size_t)b * CDIM + cb + tg) * NDIM + n;
            __half2 h0 = __floats2half2_rn(acc[nf][0], acc[nf][1]);
            __half2 h1 = __floats2half2_rn(acc[nf][2], acc[nf][3]);
            *reinterpret_cast<u32*>(&g_v16[base]) = *(u32*)&h0;
            *reinterpret_cast<u32*>(&g_v16[base + (size_t)8 * NDIM]) = *(u32*)&h1;
        }
    }

    float s0 = 0.f, q0 = 0.f, s1 = 0.f, q1 = 0.f;
#pragma unroll
    for (int nf = 0; nf < 16; nf++) {
        s0 += acc[nf][0] + acc[nf][1];
        q0 += acc[nf][0] * acc[nf][0] + acc[nf][1] * acc[nf][1];
        s1 += acc[nf][2] + acc[nf][3];
        q1 += acc[nf][2] * acc[nf][2] + acc[nf][3] * acc[nf][3];
    }
#pragma unroll
    for (int off = 1; off < 4; off <<= 1) {
        s0 += __shfl_xor_sync(0xffffffffu, s0, off);
        q0 += __shfl_xor_sync(0xffffffffu, q0, off);
        s1 += __shfl_xor_sync(0xffffffffu, s1, off);
        q1 += __shfl_xor_sync(0xffffffffu, q1, off);
    }
    if (tq == 0) {
        sm_sp[wid * 16 + tg]     = make_float2(s0, q0);
        sm_sp[wid * 16 + 8 + tg] = make_float2(s1, q1);
    }
    __syncthreads();
    if (tid < 64) {
        int wo2 = tid >> 4, c = tid & 15;
        float2 a = sm_sp[wo2 * 16 + c];
        float2 e = sm_sp[(wo2 + 4) * 16 + c];
        int ch = blockIdx.x * 64 + wo2 * 16 + c;
        g_ps1[ch * 128 + b * 8 + blockIdx.y] = a.x + e.x;
        g_ps2[ch * 128 + b * 8 + blockIdx.y] = a.y + e.y;
    }
}

// ================= Kernel 2: finalize stats =================
__global__ void __launch_bounds__(128) stats_fin(
    const float* __restrict__ qg, const float* __restrict__ qbe,
    const float* __restrict__ kg, const float* __restrict__ kbe,
    const float* __restrict__ vg, const float* __restrict__ vbe)
{
    const int ch = blockIdx.x, tid = threadIdx.x;
    __shared__ float r1[128], r2[128];
    r1[tid] = g_ps1[ch * 128 + tid];
    r2[tid] = g_ps2[ch * 128 + tid];
    __syncthreads();
    for (int off = 64; off; off >>= 1) {
        if (tid < off) { r1[tid] += r1[tid + off]; r2[tid] += r2[tid + off]; }
        __syncthreads();
    }
    if (tid == 0) {
        const float invM = 1.0f / (float)(BDIM * NDIM);
        float mean = r1[0] * invM;
        float var = r2[0] * invM - mean * mean;
        float gamma, beta;
        if (ch < 32)      { gamma = qg[ch];      beta = qbe[ch]; }
        else if (ch < 64) { gamma = kg[ch - 32]; beta = kbe[ch - 32]; }
        else              { gamma = vg[ch - 64]; beta = vbe[ch - 64]; }
        float sc = gamma * rsqrtf(var + EPSV);
        g_scale[ch] = sc;
        g_shift[ch] = beta - mean * sc;
    }
}

// ================= Kernel 3: fused Q/K transpose + V normalize (one launch) =======
// blockIdx.x < 32 : qkt work (n0 = blockIdx.x*64)
// blockIdx.x >= 32: v16 work (i4 = (blockIdx.x-32)*256 + tid)
__global__ void __launch_bounds__(256) qkv16_kernel()
{
    const int tid = threadIdx.x, b = blockIdx.y;
    if (blockIdx.x < 32) {
        __shared__ float s[64][65];
        __shared__ float scl[64], shf[64];
        const int n0 = blockIdx.x * 64;
        if (tid < 64) {
            float f = (tid < 32) ? LOG2E : 1.0f;
            scl[tid] = g_scale[tid] * f;
            shf[tid] = g_shift[tid] * f;
        }
        __syncthreads();
        for (int idx = tid; idx < 4096; idx += 256) {
            int ch = idx >> 6, nn = idx & 63;
            s[ch][nn] = g_proj[((size_t)b * 64 + ch) * NDIM + n0 + nn] * scl[ch] + shf[ch];
        }
        __syncthreads();
        const int n = tid >> 2, d0 = (tid & 3) * 8;
        const size_t row = ((size_t)b * NDIM + n0 + n) * 32;
#pragma unroll
        for (int qk = 0; qk < 2; qk++) {
            __half* dst = (qk ? g_k16 : g_q16) + row;
            u32 wh[4];
#pragma unroll
            for (int j = 0; j < 4; j++) {
                __half2 hh = __floats2half2_rn(s[qk * 32 + d0 + 2 * j][n],
                                               s[qk * 32 + d0 + 2 * j + 1][n]);
                wh[j] = *(u32*)&hh;
            }
            *reinterpret_cast<uint4*>(dst + d0) = make_uint4(wh[0], wh[1], wh[2], wh[3]);
        }
    } else {
        const int i4 = (blockIdx.x - 32) * 256 + tid;
        const int off = i4 * 4;
        const int c = off >> 11, n = off & 2047;
        const float sc = g_scale[64 + c], sh = g_shift[64 + c];
        __half* p = &g_v16[((size_t)b * CDIM + c) * NDIM + n];
        uint2 w = *reinterpret_cast<const uint2*>(p);
        __half2 h0 = *(__half2*)&w.x, h1 = *(__half2*)&w.y;
        float2 f0 = __half22float2(h0), f1 = __half22float2(h1);
        float a0 = f0.x * sc + sh, a1 = f0.y * sc + sh;
        float a2 = f1.x * sc + sh, a3 = f1.y * sc + sh;
        a0 = a0 > 0.f ? a0 : 0.2f * a0; a1 = a1 > 0.f ? a1 : 0.2f * a1;
        a2 = a2 > 0.f ? a2 : 0.2f * a2; a3 = a3 > 0.f ? a3 : 0.2f * a3;
        __half2 p0 = __floats2half2_rn(a0, a1), p1 = __floats2half2_rn(a2, a3);
        *reinterpret_cast<uint2*>(p) = make_uint2(*(u32*)&p0, *(u32*)&p1);
    }
}

// ================= Kernel 5: fp16 mma flash attention (R15 structure, 2 CTA/SM) =====
#define OFF_K0 0
#define OFF_K1 5120
#define OFF_V0 10240
#define OFF_V1 47104
#define OFF_P  83968
#define OFF_M  93184
#define OFF_L  93696
#define OFF_A  93952
#define OFF_RM 94208
#define OFF_PS 94720
#define SMEM_TOTAL 95232

__global__ void __launch_bounds__(256, 2) attn_kernel(
    const float* __restrict__ x, float* __restrict__ out)
{
    extern __shared__ __align__(16) char smc[];
    const u32 sb = smem_u32(smc);
    float* Mbuf = (float*)(smc + OFF_M);
    float* Lbuf = (float*)(smc + OFF_L);
    float* Abuf = (float*)(smc + OFF_A);
    float* Rm   = (float*)(smc + OFF_RM);
    float* Psum = (float*)(smc + OFF_PS);

    const int tid = threadIdx.x, wid = tid >> 5, lane = tid & 31;
    const int wm = wid & 3, wc = wid >> 2;
    const int tg = lane >> 2, tq = lane & 3;
    const int n0 = blockIdx.x * 64, b = blockIdx.y;
    const int r0 = 16 * wm + tg;
    const bool owner = (wc == 0 && tq == 0);

    if (tid < 64) { Mbuf[tid] = -INFINITY; Lbuf[tid] = 0.0f; }

    u32 qh[2][4];
    {
        const __half* Qg = g_q16 + ((size_t)b * NDIM + n0) * 32;
#pragma unroll
        for (int kk = 0; kk < 2; kk++) {
            int d = kk * 16 + 2 * tq;
            qh[kk][0] = *(const u32*)(Qg + (size_t)r0 * 32 + d);
            qh[kk][1] = *(const u32*)(Qg + (size_t)(r0 + 8) * 32 + d);
            qh[kk][2] = *(const u32*)(Qg + (size_t)r0 * 32 + d + 8);
            qh[kk][3] = *(const u32*)(Qg + (size_t)(r0 + 8) * 32 + d + 8);
        }
    }

    float acc[4][4][4];
#pragma unroll
    for (int mj = 0; mj < 4; mj++)
#pragma unroll
        for (int nf = 0; nf < 4; nf++)
#pragma unroll
            for (int j = 0; j < 4; j++) acc[mj][nf][j] = 0.0f;

    auto issue_tile = [&](int m0, int bf) {
        u32 kb = sb + (bf ? OFF_K1 : OFF_K0);
        u32 vb = sb + (bf ? OFF_V1 : OFF_V0);
        const __half* Kg = g_k16 + ((size_t)b * NDIM + m0) * 32;
        const __half* Vg = g_v16 + (size_t)b * CDIM * NDIM + m0;
#pragma unroll
        for (int i = 0; i < 9; i++) {
            int id = tid + i * 256;
            if (id < 256) {
                int m = id >> 2, ch = id & 3;
                CP16(kb + m * 80 + ch * 16, Kg + (size_t)m * 32 + ch * 8);
            } else {
                int j = id - 256, c = j >> 3, ch = j & 7;
                CP16(vb + c * 144 + ch * 16, Vg + (size_t)c * NDIM + ch * 8);
            }
        }
        CP_COMMIT();
    };

    issue_tile(0, 0);

    for (int t = 0; t < 32; t++) {
        const int buf = t & 1, par = t & 1;
        CP_WAIT0();
        __syncthreads();   // bar1
        if (t < 31) issue_tile((t + 1) * 64, buf ^ 1);

        // ---- S = Q K^T (base-2 units) ----
        const char* K = smc + (buf ? OFF_K1 : OFF_K0);
        float sf[4][4];
#pragma unroll
        for (int nf = 0; nf < 4; nf++) {
#pragma unroll
            for (int j = 0; j < 4; j++) sf[nf][j] = 0.0f;
            const char* krow = K + (32 * wc + 8 * nf + tg) * 80;
#pragma unroll
            for (int kk = 0; kk < 2; kk++) {
                int d = kk * 16 + 2 * tq;
                u32 bh0 = *(const u32*)(krow + d * 2);
                u32 bh1 = *(const u32*)(krow + (d + 8) * 2);
                mma16(sf[nf], qh[kk], bh0, bh1);
            }
        }

        // ---- row max; warp-pair exchange via named barrier ----
        float rm0 = fmaxf(fmaxf(sf[0][0], sf[0][1]), fmaxf(sf[1][0], sf[1][1]));
        rm0 = fmaxf(rm0, fmaxf(fmaxf(sf[2][0], sf[2][1]), fmaxf(sf[3][0], sf[3][1])));
        float rm1 = fmaxf(fmaxf(sf[0][2], sf[0][3]), fmaxf(sf[1][2], sf[1][3]));
        rm1 = fmaxf(rm1, fmaxf(fmaxf(sf[2][2], sf[2][3]), fmaxf(sf[3][2], sf[3][3])));
        rm0 = fmaxf(rm0, __shfl_xor_sync(0xffffffffu, rm0, 1));
        rm0 = fmaxf(rm0, __shfl_xor_sync(0xffffffffu, rm0, 2));
        rm1 = fmaxf(rm1, __shfl_xor_sync(0xffffffffu, rm1, 1));
        rm1 = fmaxf(rm1, __shfl_xor_sync(0xffffffffu, rm1, 2));
        if (tq == 0) { Rm[wc * 64 + r0] = rm0; Rm[wc * 64 + r0 + 8] = rm1; }
        asm volatile("bar.sync %0, 64;" :: "r"(wm + 1) : "memory");

        // ---- softmax: p = 2^(s - m) ----
        const float mo0 = Mbuf[par * 64 + r0], mo1 = Mbuf[par * 64 + r0 + 8];
        const float nm0 = fmaxf(mo0, fmaxf(Rm[r0], Rm[64 + r0]));
        const float nm1 = fmaxf(mo1, fmaxf(Rm[r0 + 8], Rm[64 + r0 + 8]));
        float lp0 = 0.0f, lp1 = 0.0f;
#pragma unroll
        for (int nf = 0; nf < 4; nf++) {
            __half2 h01 = __floats2half2_rn(ex2(sf[nf][0] - nm0), ex2(sf[nf][1] - nm0));
            __half2 h23 = __floats2half2_rn(ex2(sf[nf][2] - nm1), ex2(sf[nf][3] - nm1));
            float2 f01 = __half22float2(h01), f23 = __half22float2(h23);
            lp0 += f01.x + f01.y; lp1 += f23.x + f23.y;
            const int col = 32 * wc + 8 * nf + 2 * tq;
            *(u32*)(smc + OFF_P + r0 * 144 + col * 2) = *(u32*)&h01;
            *(u32*)(smc + OFF_P + (r0 + 8) * 144 + col * 2) = *(u32*)&h23;
        }
        lp0 += __shfl_xor_sync(0xffffffffu, lp0, 1);
        lp0 += __shfl_xor_sync(0xffffffffu, lp0, 2);
        lp1 += __shfl_xor_sync(0xffffffffu, lp1, 1);
        lp1 += __shfl_xor_sync(0xffffffffu, lp1, 2);
        if (tq == 0) { Psum[wc * 64 + r0] = lp0; Psum[wc * 64 + r0 + 8] = lp1; }
        if (owner) {
            Abuf[r0] = ex2(mo0 - nm0);
            Abuf[r0 + 8] = ex2(mo1 - nm1);
            Mbuf[(par ^ 1) * 64 + r0] = nm0;
            Mbuf[(par ^ 1) * 64 + r0 + 8] = nm1;
        }
        __syncthreads();   // bar3

        if (owner) {
            Lbuf[r0]     = Lbuf[r0]     * Abuf[r0]     + Psum[r0]     + Psum[64 + r0];
            Lbuf[r0 + 8] = Lbuf[r0 + 8] * Abuf[r0 + 8] + Psum[r0 + 8] + Psum[64 + r0 + 8];
        }

        // ---- PV ----
        const char* V = smc + (buf ? OFF_V1 : OFF_V0);
#pragma unroll
        for (int mj = 0; mj < 4; mj++) {
            const float a0 = Abuf[16 * mj + tg], a1 = Abuf[16 * mj + tg + 8];
            if (__all_sync(0xffffffffu, (a0 == 1.0f) && (a1 == 1.0f))) continue;
            const u64 A0 = dup2(a0), A1 = dup2(a1);
#pragma unroll
            for (int nf = 0; nf < 4; nf++) {
                u64* pa = reinterpret_cast<u64*>(acc[mj][nf]);
                pa[0] = mul2(pa[0], A0);
                pa[1] = mul2(pa[1], A1);
            }
        }
#pragma unroll
        for (int kk = 0; kk < 4; kk++) {
            const int m = kk * 16 + 2 * tq;
            u32 af[4][4];
#pragma unroll
            for (int mj = 0; mj < 4; mj++) {
                const int rr = 16 * mj + tg;
                af[mj][0] = *(const u32*)(smc + OFF_P + rr * 144 + m * 2);
                af[mj][1] = *(const u32*)(smc + OFF_P + (rr + 8) * 144 + m * 2);
                af[mj][2] = *(const u32*)(smc + OFF_P + rr * 144 + (m + 8) * 2);
                af[mj][3] = *(const u32*)(smc + OFF_P + (rr + 8) * 144 + (m + 8) * 2);
            }
#pragma unroll
            for (int nf = 0; nf < 4; nf++) {
                const char* vrow = V + (32 * wid + 8 * nf + tg) * 144;
                u32 b0 = *(const u32*)(vrow + m * 2);
                u32 b1 = *(const u32*)(vrow + (m + 8) * 2);
#pragma unroll
                for (int mj = 0; mj < 4; mj++)
                    mma16(acc[mj][nf], af[mj], b0, b1);
            }
        }
        // no end barrier: bar1 of iteration t+1 provides the ordering
    }
    __syncthreads();

    // ---- epilogue: O/L + residual ----
#pragma unroll
    for (int mj = 0; mj < 4; mj++) {
        const int rr = 16 * mj + tg;
        const float il0 = 1.0f / Lbuf[rr];
        const float il1 = 1.0f / Lbuf[rr + 8];
#pragma unroll
        for (int nf = 0; nf < 4; nf++) {
            const int c = 32 * wid + 8 * nf + 2 * tq;
            size_t g00 = ((size_t)b * CDIM + c) * NDIM + n0 + rr;
            size_t g01 = g00 + NDIM;
            size_t g10 = g00 + 8;
            size_t g11 = g01 + 8;
            out[g00] = acc[mj][nf][0] * il0 + x[g00];
            out[g01] = acc[mj][nf][1] * il0 + x[g01];
            out[g10] = acc[mj][nf][2] * il1 + x[g10];
            out[g11] = acc[mj][nf][3] * il1 + x[g11];
        }
    }
}

extern "C" void kernel_launch(void* const* d_in, const int* in_sizes, int n_in,
                              void* d_out, int out_size) {
    const float* x    = (const float*)d_in[0];
    const float* q_w  = (const float*)d_in[1];
    const float* q_g  = (const float*)d_in[3];
    const float* q_be = (const float*)d_in[4];
    const float* k_w  = (const float*)d_in[5];
    const float* k_g  = (const float*)d_in[7];
    const float* k_be = (const float*)d_in[8];
    const float* v_w  = (const float*)d_in[9];
    const float* v_g  = (const float*)d_in[11];
    const float* v_be = (const float*)d_in[12];
    float* out = (float*)d_out;

    w16_kernel<<<OTOT, 128>>>(q_w, k_w, v_w);
    proj16_kernel<<<dim3(5, 8, 16), 256>>>(x);
    stats_fin<<<OTOT, 128>>>(q_g, q_be, k_g, k_be, v_g, v_be);
    qkv16_kernel<<<dim3(32 + 512, 16), 256>>>();

    static int smem_set = 0;
    if (!smem_set) {
        cudaFuncSetAttribute(attn_kernel, cudaFuncAttributeMaxDynamicSharedMemorySize, SMEM_TOTAL);
        smem_set = 1;
    }
    attn_kernel<<<dim3(32, 16), 256, SMEM_TOTAL>>>(x, out);
}